// round 10
// baseline (speedup 1.0000x reference)
#include <cuda_runtime.h>
#include <cuda_fp16.h>
#include <cstdint>
#include <math.h>

// y[b,y] = softmax_l(U[y].x[b,l]) weighted sum of (F[y].x[b,l]) + fb[y]
// Fused two-GEMM + max-free online softmax, pure fp16 operands on
// mma.sync.m16n8k16. Warp tile 32x64 (128 fp32 accumulators) at occ 1:
// smem bytes/MMA drops 192 -> 128, unbinding the crossbar from the tensor pipe.

constexpr int Bn = 8, Ln = 2500, Dn = 512, Yn = 8921;
constexpr int TM = 64;                 // labels per CTA
constexpr int TN = 256;                // seq per CTA
constexpr int KC = 64;                 // k per pipeline stage
constexpr int NKC = Dn / KC;           // 8
constexpr int YT = (Yn + TM - 1) / TM; // 140
constexpr int YP = YT * TM;            // 8960
constexpr int NLT = (Ln + TN - 1) / TN;// 10
constexpr int LP = NLT * TN;           // 2560
constexpr int NG = NLT * NKC;          // 80 chunk-stages per CTA
// stage layout: U 64x64 fp16 (8KB), F (8KB), X 256x64 fp16 (32KB) = 48KB
constexpr int OFF_U = 0, OFF_F = 8192, OFF_X = 16384;
constexpr int STAGE = 49152;
constexpr int NST = 3;                 // 144KB dynamic smem -> 1 CTA/SM

// conflict-free 16B-slot swizzle within a 128B row (8 slots)
__host__ __device__ __forceinline__ int slot_sw(int row, int c) {
    return c ^ (row & 7);
}

// ---------------- fp16 scratch ----------------
__device__ __align__(16) __half g_U[(size_t)YP * Dn];
__device__ __align__(16) __half g_F[(size_t)YP * Dn];
__device__ __align__(16) __half g_X[(size_t)Bn * LP * Dn];

// ---------------- asm helpers ----------------
__device__ __forceinline__ void cpa16(uint32_t dst, const void* src) {
    asm volatile("cp.async.cg.shared.global [%0], [%1], 16;" :: "r"(dst), "l"(src));
}
__device__ __forceinline__ void cp_commit() {
    asm volatile("cp.async.commit_group;" ::: "memory");
}
template <int N>
__device__ __forceinline__ void cp_wait() {
    asm volatile("cp.async.wait_group %0;" :: "n"(N) : "memory");
}
__device__ __forceinline__ void ldm4(uint32_t& r0, uint32_t& r1, uint32_t& r2, uint32_t& r3, uint32_t a) {
    asm volatile("ldmatrix.sync.aligned.m8n8.x4.shared.b16 {%0,%1,%2,%3}, [%4];"
        : "=r"(r0), "=r"(r1), "=r"(r2), "=r"(r3) : "r"(a));
}
#define MMA_F16(d, a, bfr)                                                           \
    asm volatile("mma.sync.aligned.m16n8k16.row.col.f32.f16.f16.f32 "                \
        "{%0,%1,%2,%3},{%4,%5,%6,%7},{%8,%9},{%0,%1,%2,%3};"                         \
        : "+f"((d)[0]), "+f"((d)[1]), "+f"((d)[2]), "+f"((d)[3])                     \
        : "r"((a)[0]), "r"((a)[1]), "r"((a)[2]), "r"((a)[3]), "r"((bfr)[0]), "r"((bfr)[1]))

// ---------------- fused prep: fp32 -> fp16 for U, F, x ----------------
constexpr size_t UF_ELEMS = (size_t)YP * Dn;          // 4,587,520
constexpr size_t X_ELEMS  = (size_t)Bn * LP * Dn;     // 10,485,760
__global__ __launch_bounds__(256) void prep_all(const float* __restrict__ U,
                                                const float* __restrict__ F,
                                                const float* __restrict__ x) {
    const size_t stride = (size_t)gridDim.x * blockDim.x;
    for (size_t idx = (size_t)blockIdx.x * blockDim.x + threadIdx.x;
         idx < UF_ELEMS + X_ELEMS; idx += stride) {
        if (idx < UF_ELEMS) {
            int y = (int)(idx >> 9);
            float u = 0.f, f = 0.f;
            if (y < Yn) { u = U[idx]; f = F[idx]; }
            g_U[idx] = __float2half_rn(u);
            g_F[idx] = __float2half_rn(f);
        } else {
            size_t xi = idx - UF_ELEMS;
            size_t bl = xi >> 9;
            int l = (int)(bl % LP);
            int b = (int)(bl / LP);
            int d = (int)(xi & 511);
            float v = 0.f;
            if (l < Ln) v = x[((size_t)b * Ln + l) * Dn + d];
            g_X[xi] = __float2half_rn(v);
        }
    }
}

// ---------------- main fused kernel ----------------
__global__ __launch_bounds__(256, 1)
void attn_main(const float* __restrict__ fb, float* __restrict__ out) {
    extern __shared__ __align__(128) char smem[];
    uint32_t sbase;
    asm("{ .reg .u64 t; cvta.to.shared.u64 t, %1; cvt.u32.u64 %0, t; }" : "=r"(sbase) : "l"(smem));

    const int tid = threadIdx.x;
    const int wid = tid >> 5, lane = tid & 31;
    const int wm = wid >> 2, wn = wid & 3;       // warp grid 2(M) x 4(N); warp tile 32x64
    const int yt = blockIdx.x, b = blockIdx.y;

    // ---- loader mapping: 8 threads per 128B row ----
    const int lr0 = tid >> 3;                   // 0..31
    const int lcc = tid & 7;                    // 16B chunk in 128B row

    auto issue = [&](int gi) {
        const int ci = gi & 7, lti = gi >> 3;
        const uint32_t sb = sbase + (uint32_t)(gi % NST) * STAGE;
        #pragma unroll
        for (int rr = 0; rr < 2; rr++) {
            const int row = lr0 + rr * 32;
            const uint32_t d = (uint32_t)row * 128 + (uint32_t)(slot_sw(row, lcc) << 4);
            const size_t s = ((size_t)(yt * TM + row)) * Dn + (size_t)ci * KC + lcc * 8;
            cpa16(sb + OFF_U + d, g_U + s);
            cpa16(sb + OFF_F + d, g_F + s);
        }
        #pragma unroll
        for (int rr = 0; rr < 8; rr++) {
            const int row = lr0 + rr * 32;
            const uint32_t d = (uint32_t)row * 128 + (uint32_t)(slot_sw(row, lcc) << 4);
            const size_t s = ((size_t)b * LP + (size_t)lti * TN + row) * Dn + (size_t)ci * KC + lcc * 8;
            cpa16(sb + OFF_X + d, g_X + s);
        }
    };

    // ---- ldmatrix per-thread invariants ----
    const int lg = lane >> 3, lr = lane & 7;
    const int rA0 = wm * 32 + lr + (lg & 1) * 8;        // A: grp bit0 = row half, bit1 = k half
    const int cA = lg >> 1;
    const int rB0 = wn * 64 + lr + (lg >> 1) * 8;       // B: grp bit1 = n half, bit0 = k half
    const int cB = lg & 1;

    // hoisted ldmatrix offsets: A [kk][mt], X [kk][bt]
    uint32_t offA[4][2], offB[4][4];
    #pragma unroll
    for (int kk = 0; kk < 4; kk++) {
        #pragma unroll
        for (int t2 = 0; t2 < 2; t2++) {
            const int ra = rA0 + t2 * 16;
            offA[kk][t2] = (uint32_t)ra * 128 + (uint32_t)(slot_sw(ra, kk * 2 + cA) << 4);
        }
        #pragma unroll
        for (int bt = 0; bt < 4; bt++) {
            const int rb = rB0 + bt * 16;
            offB[kk][bt] = (uint32_t)rb * 128 + (uint32_t)(slot_sw(rb, kk * 2 + cB) << 4);
        }
    }

    const int quad = lane >> 2, tc = lane & 3;

    float z[4] = {0.f, 0.f, 0.f, 0.f}, nw[4] = {0.f, 0.f, 0.f, 0.f};

    // prologue: 2 stages in flight (3-buffer ring)
    issue(0); cp_commit();
    issue(1); cp_commit();

    for (int lt = 0; lt < NLT; lt++) {
        float accS[2][8][4], accT[2][8][4];
        #pragma unroll
        for (int mt = 0; mt < 2; mt++)
            #pragma unroll
            for (int nt = 0; nt < 8; nt++)
                #pragma unroll
                for (int j = 0; j < 4; j++) { accS[mt][nt][j] = 0.f; accT[mt][nt][j] = 0.f; }

        for (int c = 0; c < NKC; c++) {
            const int g = lt * NKC + c;
            cp_wait<1>();
            __syncthreads();
            const int gi = g + 2;
            if (gi < NG) issue(gi);
            cp_commit();

            const uint32_t sb = sbase + (uint32_t)(g % NST) * STAGE;
            #pragma unroll
            for (int kk = 0; kk < 4; kk++) {
                uint32_t X[8][2], A0[2][4], A1[2][4];
                #pragma unroll
                for (int bt = 0; bt < 4; bt++)
                    ldm4(X[bt*2][0], X[bt*2][1], X[bt*2+1][0], X[bt*2+1][1], sb + OFF_X + offB[kk][bt]);
                #pragma unroll
                for (int mt = 0; mt < 2; mt++) {
                    ldm4(A0[mt][0], A0[mt][1], A0[mt][2], A0[mt][3], sb + OFF_U + offA[kk][mt]);
                    ldm4(A1[mt][0], A1[mt][1], A1[mt][2], A1[mt][3], sb + OFF_F + offA[kk][mt]);
                }
                #pragma unroll
                for (int mt = 0; mt < 2; mt++)
                    #pragma unroll
                    for (int nt = 0; nt < 8; nt++) {
                        MMA_F16(accS[mt][nt], A0[mt], X[nt]);
                        MMA_F16(accT[mt][nt], A1[mt], X[nt]);
                    }
            }
        }

        // max-free softmax partial update (scores bounded ~|2|)
        #pragma unroll
        for (int nt = 0; nt < 8; nt++)
            #pragma unroll
            for (int j = 0; j < 4; j++) {
                const int l = lt * TN + wn * 64 + nt * 8 + tc * 2 + (j & 1);
                const bool v = (l < Ln);
                #pragma unroll
                for (int mt = 0; mt < 2; mt++) {
                    const int zi = mt * 2 + (j >> 1);
                    const float e = v ? __expf(accS[mt][nt][j]) : 0.f;
                    z[zi] += e;
                    nw[zi] = fmaf(e, accT[mt][nt][j], nw[zi]);
                }
            }
    }

    // ---- final reduction ----
    cp_wait<0>();
    __syncthreads();
    #pragma unroll
    for (int zi = 0; zi < 4; zi++) {
        z[zi]  += __shfl_xor_sync(0xffffffffu, z[zi], 1);
        z[zi]  += __shfl_xor_sync(0xffffffffu, z[zi], 2);
        nw[zi] += __shfl_xor_sync(0xffffffffu, nw[zi], 1);
        nw[zi] += __shfl_xor_sync(0xffffffffu, nw[zi], 2);
    }
    float2* red = (float2*)smem;   // [4 warp_n][64 rows]
    if (tc == 0) {
        #pragma unroll
        for (int zi = 0; zi < 4; zi++) {
            const int mt = zi >> 1, rh = zi & 1;
            const int row = wm * 32 + mt * 16 + rh * 8 + quad;
            red[wn * 64 + row] = make_float2(z[zi], nw[zi]);
        }
    }
    __syncthreads();
    if (tid < 64) {
        float zz = 0.f, nn = 0.f;
        #pragma unroll
        for (int w = 0; w < 4; w++) { float2 v = red[w * 64 + tid]; zz += v.x; nn += v.y; }
        const int y = yt * TM + tid;
        if (y < Yn) out[(size_t)b * Yn + y] = nn / zz + fb[y];
    }
}

// ---------------- host launch ----------------
extern "C" void kernel_launch(void* const* d_in, const int* in_sizes, int n_in,
                              void* d_out, int out_size) {
    const float* x  = (const float*)d_in[0];
    const float* Uw = (const float*)d_in[1];
    const float* Fw = (const float*)d_in[2];
    const float* fb = (const float*)d_in[3];
    float* out = (float*)d_out;
    (void)in_sizes; (void)n_in; (void)out_size;

    prep_all<<<4096, 256>>>(Uw, Fw, x);

    cudaFuncSetAttribute(attn_main, cudaFuncAttributeMaxDynamicSharedMemorySize, NST * STAGE);
    attn_main<<<dim3(YT, Bn), 256, NST * STAGE>>>(fb, out);
}

// round 11
// speedup vs baseline: 1.1641x; 1.1641x over previous
#include <cuda_runtime.h>
#include <cuda_fp16.h>
#include <cstdint>
#include <math.h>

// y[b,y] = softmax_l(U[y].x[b,l]) weighted sum of (F[y].x[b,l]) + fb[y]
// Fused two-GEMM + max-free online softmax, fp16 operands on mma.sync.m16n8k16.
// Persistent CTAs: 296 CTAs (2/SM) each stream 3-4 (yt,b) tiles through ONE
// continuous 3-stage cp.async ring (no inter-wave pipeline drain).
// U is pre-multiplied by log2(e); epilogue uses raw ex2.approx.

constexpr int Bn = 8, Ln = 2500, Dn = 512, Yn = 8921;
constexpr int TM = 64;                 // labels per CTA tile
constexpr int TN = 128;                // seq per CTA tile
constexpr int KC = 64;                 // k per pipeline stage
constexpr int NKC = Dn / KC;           // 8
constexpr int YT = (Yn + TM - 1) / TM; // 140
constexpr int YP = YT * TM;            // 8960
constexpr int NLT = (Ln + TN - 1) / TN;// 20
constexpr int LP = NLT * TN;           // 2560
constexpr int NG = NLT * NKC;          // 160 chunks per tile
constexpr int NTILE = YT * Bn;         // 1120
constexpr int NSLOT = 296;             // persistent CTAs (2 per SM x 148)
// stage: U 64x64 fp16 (8KB), F (8KB), X 128x64 fp16 (16KB) = 32KB
constexpr int OFF_U = 0, OFF_F = 8192, OFF_X = 16384;
constexpr int STAGE = 32768;
constexpr int NST = 3;                 // ring depth; + 2KB reduce buffer

// conflict-free 16B-slot swizzle within a 128B row (8 slots)
__host__ __device__ __forceinline__ int slot_sw(int row, int c) {
    return c ^ (row & 7);
}

// ---------------- fp16 scratch ----------------
__device__ __align__(16) __half g_U[(size_t)YP * Dn];   // pre-scaled by log2(e)
__device__ __align__(16) __half g_F[(size_t)YP * Dn];
__device__ __align__(16) __half g_X[(size_t)Bn * LP * Dn];

// ---------------- asm helpers ----------------
__device__ __forceinline__ void cpa16(uint32_t dst, const void* src) {
    asm volatile("cp.async.cg.shared.global [%0], [%1], 16;" :: "r"(dst), "l"(src));
}
__device__ __forceinline__ void cp_commit() {
    asm volatile("cp.async.commit_group;" ::: "memory");
}
template <int N>
__device__ __forceinline__ void cp_wait() {
    asm volatile("cp.async.wait_group %0;" :: "n"(N) : "memory");
}
__device__ __forceinline__ void ldm4(uint32_t& r0, uint32_t& r1, uint32_t& r2, uint32_t& r3, uint32_t a) {
    asm volatile("ldmatrix.sync.aligned.m8n8.x4.shared.b16 {%0,%1,%2,%3}, [%4];"
        : "=r"(r0), "=r"(r1), "=r"(r2), "=r"(r3) : "r"(a));
}
__device__ __forceinline__ float ex2f(float x) {
    float r;
    asm("ex2.approx.f32 %0, %1;" : "=f"(r) : "f"(x));
    return r;
}
#define MMA_F16(d, a, bfr)                                                           \
    asm volatile("mma.sync.aligned.m16n8k16.row.col.f32.f16.f16.f32 "                \
        "{%0,%1,%2,%3},{%4,%5,%6,%7},{%8,%9},{%0,%1,%2,%3};"                         \
        : "+f"((d)[0]), "+f"((d)[1]), "+f"((d)[2]), "+f"((d)[3])                     \
        : "r"((a)[0]), "r"((a)[1]), "r"((a)[2]), "r"((a)[3]), "r"((bfr)[0]), "r"((bfr)[1]))

// ---------------- fused prep: fp32 -> fp16 (U scaled by log2 e) ----------------
constexpr size_t UF_ELEMS = (size_t)YP * Dn;
constexpr size_t X_ELEMS  = (size_t)Bn * LP * Dn;
__global__ __launch_bounds__(256) void prep_all(const float* __restrict__ U,
                                                const float* __restrict__ F,
                                                const float* __restrict__ x) {
    const size_t stride = (size_t)gridDim.x * blockDim.x;
    for (size_t idx = (size_t)blockIdx.x * blockDim.x + threadIdx.x;
         idx < UF_ELEMS + X_ELEMS; idx += stride) {
        if (idx < UF_ELEMS) {
            int y = (int)(idx >> 9);
            float u = 0.f, f = 0.f;
            if (y < Yn) { u = U[idx] * 1.4426950408889634f; f = F[idx]; }
            g_U[idx] = __float2half_rn(u);
            g_F[idx] = __float2half_rn(f);
        } else {
            size_t xi = idx - UF_ELEMS;
            size_t bl = xi >> 9;
            int l = (int)(bl % LP);
            int b = (int)(bl / LP);
            int d = (int)(xi & 511);
            float v = 0.f;
            if (l < Ln) v = x[((size_t)b * Ln + l) * Dn + d];
            g_X[xi] = __float2half_rn(v);
        }
    }
}

// ---------------- main fused persistent kernel ----------------
__global__ __launch_bounds__(256, 2)
void attn_main(const float* __restrict__ fb, float* __restrict__ out) {
    extern __shared__ __align__(128) char smem[];
    uint32_t sbase;
    asm("{ .reg .u64 t; cvta.to.shared.u64 t, %1; cvt.u32.u64 %0, t; }" : "=r"(sbase) : "l"(smem));
    float2* red = (float2*)(smem + NST * STAGE);   // [4 wn][64 rows], above the ring

    const int tid = threadIdx.x;
    const int wid = tid >> 5, lane = tid & 31;
    const int wm = wid >> 2, wn = wid & 3;        // warp grid 2(M) x 4(N), tile 32x32
    const int cta = blockIdx.x;

    // ---- loader mapping: 8 threads per 128B row ----
    const int lr0 = tid >> 3;                     // 0..31
    const int lcc = tid & 7;                      // 16B chunk in 128B row

    // ---- producer state (continuous chunk stream across tiles) ----
    int p_t = cta;
    int p_rem = 0;                                // 0..NG-1 within tile
    int p_slot = 0;
    const __half* p_u = g_U + (size_t)(p_t % YT) * TM * Dn;
    const __half* p_f = g_F + (size_t)(p_t % YT) * TM * Dn;
    const __half* p_x = g_X + (size_t)(p_t / YT) * LP * Dn;

    auto produce = [&]() {
        if (p_t < NTILE) {
            const int ci = p_rem & 7, lti = p_rem >> 3;
            const uint32_t sb = sbase + (uint32_t)p_slot * STAGE;
            #pragma unroll
            for (int rr = 0; rr < 2; rr++) {
                const int row = lr0 + rr * 32;
                const uint32_t d = (uint32_t)row * 128 + (uint32_t)(slot_sw(row, lcc) << 4);
                const size_t s = (size_t)row * Dn + (size_t)ci * KC + lcc * 8;
                cpa16(sb + OFF_U + d, p_u + s);
                cpa16(sb + OFF_F + d, p_f + s);
            }
            #pragma unroll
            for (int rr = 0; rr < 4; rr++) {
                const int row = lr0 + rr * 32;
                const uint32_t d = (uint32_t)row * 128 + (uint32_t)(slot_sw(row, lcc) << 4);
                const size_t s = ((size_t)lti * TN + row) * Dn + (size_t)ci * KC + lcc * 8;
                cpa16(sb + OFF_X + d, p_x + s);
            }
            p_slot = (p_slot == NST - 1) ? 0 : p_slot + 1;
            if (++p_rem == NG) {
                p_rem = 0;
                p_t += NSLOT;
                if (p_t < NTILE) {
                    p_u = g_U + (size_t)(p_t % YT) * TM * Dn;
                    p_f = g_F + (size_t)(p_t % YT) * TM * Dn;
                    p_x = g_X + (size_t)(p_t / YT) * LP * Dn;
                }
            }
        }
        cp_commit();   // commit even when exhausted to keep wait_group counts aligned
    };

    // ---- ldmatrix per-thread invariants ----
    const int lg = lane >> 3, lr = lane & 7;
    const int rA0 = wm * 32 + lr + (lg & 1) * 8;
    const int cA = lg >> 1;
    const int rB0 = wn * 32 + lr + (lg >> 1) * 8;
    const int cB = lg & 1;
    // base offsets (kk=0); off[kk] = off0 ^ (kk<<5) since slot = (kk*2)|c ^ (row&7)
    uint32_t offA0[2], offB0[2];
    #pragma unroll
    for (int t2 = 0; t2 < 2; t2++) {
        const int ra = rA0 + t2 * 16;
        offA0[t2] = (uint32_t)ra * 128 + (uint32_t)(slot_sw(ra, cA) << 4);
        const int rb = rB0 + t2 * 16;
        offB0[t2] = (uint32_t)rb * 128 + (uint32_t)(slot_sw(rb, cB) << 4);
    }

    const int quad = lane >> 2, tc = lane & 3;

    // prologue: 2 stages in flight
    produce();
    produce();

    int c_slot = 0;
    for (int t = cta; t < NTILE; t += NSLOT) {
        const int yt = t % YT, b = t / YT;
        float z[4] = {0.f, 0.f, 0.f, 0.f}, nw[4] = {0.f, 0.f, 0.f, 0.f};

        for (int lt = 0; lt < NLT; lt++) {
            float accS[2][4][4], accT[2][4][4];
            #pragma unroll
            for (int mt = 0; mt < 2; mt++)
                #pragma unroll
                for (int nt = 0; nt < 4; nt++)
                    #pragma unroll
                    for (int j = 0; j < 4; j++) { accS[mt][nt][j] = 0.f; accT[mt][nt][j] = 0.f; }

            for (int c = 0; c < NKC; c++) {
                cp_wait<1>();
                __syncthreads();
                produce();

                const uint32_t sb = sbase + (uint32_t)c_slot * STAGE;
                c_slot = (c_slot == NST - 1) ? 0 : c_slot + 1;
                #pragma unroll
                for (int kk = 0; kk < 4; kk++) {
                    uint32_t X[4][2], A0[2][4], A1[2][4];
                    #pragma unroll
                    for (int bt = 0; bt < 2; bt++)
                        ldm4(X[bt*2][0], X[bt*2][1], X[bt*2+1][0], X[bt*2+1][1],
                             sb + OFF_X + (offB0[bt] ^ (kk << 5)));
                    #pragma unroll
                    for (int mt = 0; mt < 2; mt++) {
                        ldm4(A0[mt][0], A0[mt][1], A0[mt][2], A0[mt][3],
                             sb + OFF_U + (offA0[mt] ^ (kk << 5)));
                        ldm4(A1[mt][0], A1[mt][1], A1[mt][2], A1[mt][3],
                             sb + OFF_F + (offA0[mt] ^ (kk << 5)));
                    }
                    #pragma unroll
                    for (int mt = 0; mt < 2; mt++)
                        #pragma unroll
                        for (int nt = 0; nt < 4; nt++) {
                            MMA_F16(accS[mt][nt], A0[mt], X[nt]);
                            MMA_F16(accT[mt][nt], A1[mt], X[nt]);
                        }
                }
            }

            // max-free softmax partial update (log2-domain scores, ex2)
            #pragma unroll
            for (int nt = 0; nt < 4; nt++)
                #pragma unroll
                for (int j = 0; j < 4; j++) {
                    const int l = lt * TN + wn * 32 + nt * 8 + tc * 2 + (j & 1);
                    const bool v = (l < Ln);
                    #pragma unroll
                    for (int mt = 0; mt < 2; mt++) {
                        const int zi = mt * 2 + (j >> 1);
                        const float e = v ? ex2f(accS[mt][nt][j]) : 0.f;
                        z[zi] += e;
                        nw[zi] = fmaf(e, accT[mt][nt][j], nw[zi]);
                    }
                }
        }

        // ---- per-tile output (ring keeps streaming; red is a disjoint region) ----
        #pragma unroll
        for (int zi = 0; zi < 4; zi++) {
            z[zi]  += __shfl_xor_sync(0xffffffffu, z[zi], 1);
            z[zi]  += __shfl_xor_sync(0xffffffffu, z[zi], 2);
            nw[zi] += __shfl_xor_sync(0xffffffffu, nw[zi], 1);
            nw[zi] += __shfl_xor_sync(0xffffffffu, nw[zi], 2);
        }
        if (tc == 0) {
            #pragma unroll
            for (int zi = 0; zi < 4; zi++) {
                const int mt = zi >> 1, rh = zi & 1;
                const int row = wm * 32 + mt * 16 + rh * 8 + quad;
                red[wn * 64 + row] = make_float2(z[zi], nw[zi]);
            }
        }
        __syncthreads();
        if (tid < 64) {
            float zz = 0.f, nn = 0.f;
            #pragma unroll
            for (int w = 0; w < 4; w++) { float2 v = red[w * 64 + tid]; zz += v.x; nn += v.y; }
            const int y = yt * TM + tid;
            if (y < Yn) out[(size_t)b * Yn + y] = nn / zz + fb[y];
        }
        __syncthreads();   // red reusable next tile
    }
    cp_wait<0>();
}

// ---------------- host launch ----------------
extern "C" void kernel_launch(void* const* d_in, const int* in_sizes, int n_in,
                              void* d_out, int out_size) {
    const float* x  = (const float*)d_in[0];
    const float* Uw = (const float*)d_in[1];
    const float* Fw = (const float*)d_in[2];
    const float* fb = (const float*)d_in[3];
    float* out = (float*)d_out;
    (void)in_sizes; (void)n_in; (void)out_size;

    prep_all<<<4096, 256>>>(Uw, Fw, x);

    const int dyn = NST * STAGE + 2048;
    cudaFuncSetAttribute(attn_main, cudaFuncAttributeMaxDynamicSharedMemorySize, dyn);
    attn_main<<<NSLOT, 256, dyn>>>(fb, out);
}